// round 5
// baseline (speedup 1.0000x reference)
#include <cuda_runtime.h>
#include <math.h>

#define MARGIN 0.2f
#define EPS_V 1e-6f
#define MAXG 16384   // max triplet blocks (B/8)

// Per-block partial sums (device globals; no allocation allowed)
__device__ float g_bs[MAXG];
__device__ float g_bc[MAXG];

// ---------------------------------------------------------------------------
// K1: one warp per row, self-contained mining via warp-ballot scans over the
// L1/L2-resident label/zidx arrays (no prep kernel, no global tables).
// a-row (the only DRAM-streaming operand) is prefetched into a float4[8]
// register array first -> 8 back-to-back LDG.128 per warp (high MLP); the
// scans execute while those loads are in flight.
// ---------------------------------------------------------------------------
__global__ void __launch_bounds__(256) triplet_kernel(const float* __restrict__ z,
                                                      const int* __restrict__ label,
                                                      const int* __restrict__ zidx,
                                                      int B, int C, int k) {
    const int warp = threadIdx.x >> 5;
    const int lane = threadIdx.x & 31;
    const int i = blockIdx.x * 8 + warp;

    __shared__ float s_s[8];
    __shared__ float s_c[8];

    float per = 0.0f, vld = 0.0f;

    if (i < B) {
        // ---- start streaming the a-row immediately (evict-first) ----
        float4 av[8];
        const bool fast = (C == 1024);
        const float4* a = (const float4*)(z + (size_t)i * C);
        if (fast) {
            #pragma unroll
            for (int u = 0; u < 8; u++)
                av[u] = __ldcs(&a[lane + (u << 5)]);
        }

        const int lab_i = __ldg(&label[i]);
        const int l0    = __ldg(&label[0]);
        const int idx_i = __ldg(&zidx[i]);

        // ---- neg index (+ allsame verdict as a by-product) ----
        int neg = -1;
        bool allsame = false;
        if (lab_i != l0) {
            neg = 0;                        // label[0] differs from lab_i
        } else {
            // first j with label[j] != l0 (expected ~1 step for random labels)
            int jd = -1;
            for (int base = 0; base < B; base += 32) {
                int j = base + lane;
                int lj = (j < B) ? __ldg(&label[j]) : l0;
                unsigned m = __ballot_sync(0xffffffffu, lj != l0);
                if (m) { jd = base + __ffs(m) - 1; break; }
            }
            if (jd >= 0) neg = jd;
            else         allsame = true;    // no different label anywhere
        }

        // ---- pos index ----
        int pos = -1;
        if (!allsame) {
            // first j: label[j]==lab_i && zidx[j]!=idx_i (expected ~8 steps)
            for (int base = 0; base < B; base += 32) {
                int j = base + lane;
                bool ok = false;
                if (j < B) {
                    int lj = __ldg(&label[j]);
                    ok = (lj == lab_i) && (__ldg(&zidx[j]) != idx_i);
                }
                unsigned m = __ballot_sync(0xffffffffu, ok);
                if (m) { pos = base + __ffs(m) - 1; break; }
            }
        } else {
            // all labels equal: effective labels are -1 for j<k, l0 otherwise
            const int eff_i = (i < k) ? -1 : l0;
            neg = (i < k) ? ((k < B) ? k : -1) : 0;
            for (int base = 0; base < B; base += 32) {
                int j = base + lane;
                bool ok = false;
                if (j < B) {
                    int effj = (j < k) ? -1 : l0;
                    ok = (effj == eff_i) && (__ldg(&zidx[j]) != idx_i);
                }
                unsigned m = __ballot_sync(0xffffffffu, ok);
                if (m) { pos = base + __ffs(m) - 1; break; }
            }
        }

        const bool valid = (pos >= 0) && (neg >= 0);
        if (valid) {
            const float4* p = (const float4*)(z + (size_t)pos * C);
            const float4* n = (const float4*)(z + (size_t)neg * C);

            float sap = 0.0f, san = 0.0f;
            if (fast) {
                #pragma unroll
                for (int u = 0; u < 8; u++) {
                    const int v = lane + (u << 5);
                    float4 pv = __ldg(&p[v]);
                    float4 nv = __ldg(&n[v]);
                    float d;
                    d = av[u].x - pv.x + EPS_V; sap = fmaf(d, d, sap);
                    d = av[u].y - pv.y + EPS_V; sap = fmaf(d, d, sap);
                    d = av[u].z - pv.z + EPS_V; sap = fmaf(d, d, sap);
                    d = av[u].w - pv.w + EPS_V; sap = fmaf(d, d, sap);
                    d = av[u].x - nv.x + EPS_V; san = fmaf(d, d, san);
                    d = av[u].y - nv.y + EPS_V; san = fmaf(d, d, san);
                    d = av[u].z - nv.z + EPS_V; san = fmaf(d, d, san);
                    d = av[u].w - nv.w + EPS_V; san = fmaf(d, d, san);
                }
            } else {
                const int nvec = C >> 2;
                for (int v = lane; v < nvec; v += 32) {
                    float4 avv = __ldcs(&a[v]);
                    float4 pv = __ldg(&p[v]);
                    float4 nv = __ldg(&n[v]);
                    float d;
                    d = avv.x - pv.x + EPS_V; sap = fmaf(d, d, sap);
                    d = avv.y - pv.y + EPS_V; sap = fmaf(d, d, sap);
                    d = avv.z - pv.z + EPS_V; sap = fmaf(d, d, sap);
                    d = avv.w - pv.w + EPS_V; sap = fmaf(d, d, sap);
                    d = avv.x - nv.x + EPS_V; san = fmaf(d, d, san);
                    d = avv.y - nv.y + EPS_V; san = fmaf(d, d, san);
                    d = avv.z - nv.z + EPS_V; san = fmaf(d, d, san);
                    d = avv.w - nv.w + EPS_V; san = fmaf(d, d, san);
                }
            }
            #pragma unroll
            for (int o = 16; o > 0; o >>= 1) {
                sap += __shfl_xor_sync(0xffffffffu, sap, o);
                san += __shfl_xor_sync(0xffffffffu, san, o);
            }
            per = fmaxf(sqrtf(sap) - sqrtf(san) + MARGIN, 0.0f);
            vld = 1.0f;
        }
    }

    // ---- per-block partial sum (deterministic fixed order) ----
    if (lane == 0) { s_s[warp] = per; s_c[warp] = vld; }
    __syncthreads();
    if (threadIdx.x == 0) {
        float s = 0.0f, c = 0.0f;
        #pragma unroll
        for (int w = 0; w < 8; w++) { s += s_s[w]; c += s_c[w]; }
        g_bs[blockIdx.x] = s;
        g_bc[blockIdx.x] = c;
    }
}

// ---------------------------------------------------------------------------
// K2: deterministic single-block reduction of per-block partials -> scalar.
// ---------------------------------------------------------------------------
__global__ void __launch_bounds__(256) finalize_kernel(float* __restrict__ out,
                                                       int nblocks) {
    cudaGridDependencySynchronize();
    __shared__ float s_s[256];
    __shared__ float s_c[256];
    const int tid = threadIdx.x;
    float s = 0.0f, c = 0.0f;
    for (int b = tid; b < nblocks; b += 256) { s += g_bs[b]; c += g_bc[b]; }
    s_s[tid] = s; s_c[tid] = c;
    __syncthreads();
    #pragma unroll
    for (int o = 128; o > 0; o >>= 1) {
        if (tid < o) { s_s[tid] += s_s[tid + o]; s_c[tid] += s_c[tid + o]; }
        __syncthreads();
    }
    if (tid == 0) out[0] = (s_c[0] > 0.0f) ? (s_s[0] / s_c[0]) : 0.0f;
}

extern "C" void kernel_launch(void* const* d_in, const int* in_sizes, int n_in,
                              void* d_out, int out_size) {
    const int* z_label = (const int*)d_in[0];
    const int* z_idx   = (const int*)d_in[1];
    const float* z     = (const float*)d_in[2];
    float* out = (float*)d_out;

    const int B = in_sizes[0];
    const int C = in_sizes[2] / B;
    int k = (int)((double)B * 0.01);
    if (k < 2) k = 2;

    int nblocks = (B + 7) / 8;
    if (nblocks > MAXG) nblocks = MAXG;   // (B <= 8192 in practice)

    triplet_kernel<<<nblocks, 256>>>(z, z_label, z_idx, B, C, k);

    // finalize with PDL: launches/sets up while triplet drains, syncs inside
    {
        cudaLaunchConfig_t cfg = {};
        cfg.gridDim = dim3(1);
        cfg.blockDim = dim3(256);
        cfg.dynamicSmemBytes = 0;
        cfg.stream = 0;
        cudaLaunchAttribute at[1];
        at[0].id = cudaLaunchAttributeProgrammaticStreamSerialization;
        at[0].val.programmaticStreamSerializationAllowed = 1;
        cfg.attrs = at;
        cfg.numAttrs = 1;
        cudaLaunchKernelEx(&cfg, finalize_kernel, out, nblocks);
    }
}

// round 6
// speedup vs baseline: 1.2088x; 1.2088x over previous
#include <cuda_runtime.h>
#include <math.h>

#define MARGIN 0.2f
#define EPS_V  1e-6f
#define ENC(i) (0x7FFFFFFF - (i))

// All scratch is zero-init at load AND reset to zero by the last triplet block
// each run, so every graph replay sees the same initial state.
__device__ int                g_first_enc[256];  // 0 = label absent; else ENC(first idx)
__device__ int                g_mfirst_enc;      // 0 = all labels identical
__device__ unsigned long long g_sum;             // fixed-point 2^32 sum of per
__device__ unsigned int       g_cnt;             // valid count
__device__ unsigned int       g_done;            // completed-block counter

// ---------------------------------------------------------------------------
// K1: multi-block prep. Global atomics spread across L2 (no single-SM ATOMS
// bottleneck). first-occurrence per raw label + first index whose label != l0.
// ---------------------------------------------------------------------------
__global__ void __launch_bounds__(256) prep_kernel(const int* __restrict__ label, int B) {
    const int i    = blockIdx.x * 256 + threadIdx.x;
    const int lane = threadIdx.x & 31;
    const int l0   = __ldg(&label[0]);

    const int lab = (i < B) ? __ldg(&label[i]) : l0;
    if (i < B)
        atomicMax(&g_first_enc[lab & 255], ENC(i));

    unsigned m = __ballot_sync(0xffffffffu, (i < B) && (lab != l0));
    if (lane == 0 && m) {
        int j = (i - lane) + __ffs(m) - 1;
        atomicMax(&g_mfirst_enc, ENC(j));
    }
}

// ---------------------------------------------------------------------------
// K2: one warp per row + fused deterministic reduction tail.
// ---------------------------------------------------------------------------
__global__ void __launch_bounds__(256) triplet_kernel(const float* __restrict__ z,
                                                      const int* __restrict__ label,
                                                      const int* __restrict__ zidx,
                                                      float* __restrict__ out,
                                                      int B, int C, int k,
                                                      unsigned int nblocks) {
    const int warp = threadIdx.x >> 5;
    const int lane = threadIdx.x & 31;
    const int i = blockIdx.x * 8 + warp;

    // ---- independent of prep: prefetch a-row + scalars (overlaps prep) ----
    float4 av[8];
    const bool fast = (C == 1024) && (i < B);
    const float4* a = (const float4*)(z + (size_t)((i < B) ? i : 0) * C);
    if (fast) {
        #pragma unroll
        for (int u = 0; u < 8; u++)
            av[u] = a[lane + (u << 5)];
    }
    const int lab_i = (i < B) ? __ldg(&label[i]) : 0;
    const int l0    = __ldg(&label[0]);
    const int idx_i = (i < B) ? __ldg(&zidx[i]) : 0;

    // ---- wait for prep ----
    cudaGridDependencySynchronize();

    float per = 0.0f;
    unsigned int vld = 0u;

    if (i < B) {
        const bool allsame = (g_mfirst_enc == 0);
        int pos = -1, neg = -1;

        if (!allsame) {
            const int f = 0x7FFFFFFF - g_first_enc[lab_i & 255];
            if (f != i) {
                pos = f;   // first occurrence, zidx differs (arange-like or checked below)
                if (__ldg(&zidx[f]) == idx_i) pos = -1;   // degenerate: treat via scan
            }
            if (pos < 0) {
                // i is (or behaves as) the first occurrence: scan forward for
                // the next j with same label and different zidx. Rare (~256 warps).
                for (int base = i + 1; base < B; base += 32) {
                    int j = base + lane;
                    bool ok = false;
                    if (j < B)
                        ok = (__ldg(&label[j]) == lab_i) && (__ldg(&zidx[j]) != idx_i);
                    unsigned m = __ballot_sync(0xffffffffu, ok);
                    if (m) { pos = base + __ffs(m) - 1; break; }
                }
            }
            neg = (lab_i != l0) ? 0 : (0x7FFFFFFF - g_mfirst_enc);
        } else {
            // all labels equal: effective labels are -1 for j<k, l0 otherwise.
            if (i < k) { pos = (i == 0) ? 1 : 0;          neg = k; }
            else       { pos = (i == k) ? (k + 1) : k;    neg = 0; }
            if (pos >= B || neg >= B || k < 2) { pos = -1; }
        }

        if (pos >= 0 && pos < B && neg >= 0 && neg < B) {
            const float4* p = (const float4*)(z + (size_t)pos * C);
            const float4* n = (const float4*)(z + (size_t)neg * C);
            float sap = 0.0f, san = 0.0f;
            if (fast) {
                #pragma unroll
                for (int u = 0; u < 8; u++) {
                    const int v = lane + (u << 5);
                    float4 pv = __ldg(&p[v]);
                    float4 nv = __ldg(&n[v]);
                    float d;
                    d = av[u].x - pv.x + EPS_V; sap = fmaf(d, d, sap);
                    d = av[u].y - pv.y + EPS_V; sap = fmaf(d, d, sap);
                    d = av[u].z - pv.z + EPS_V; sap = fmaf(d, d, sap);
                    d = av[u].w - pv.w + EPS_V; sap = fmaf(d, d, sap);
                    d = av[u].x - nv.x + EPS_V; san = fmaf(d, d, san);
                    d = av[u].y - nv.y + EPS_V; san = fmaf(d, d, san);
                    d = av[u].z - nv.z + EPS_V; san = fmaf(d, d, san);
                    d = av[u].w - nv.w + EPS_V; san = fmaf(d, d, san);
                }
            } else {
                const int nvec = C >> 2;
                for (int v = lane; v < nvec; v += 32) {
                    float4 avv = a[v];
                    float4 pv = __ldg(&p[v]);
                    float4 nv = __ldg(&n[v]);
                    float d;
                    d = avv.x - pv.x + EPS_V; sap = fmaf(d, d, sap);
                    d = avv.y - pv.y + EPS_V; sap = fmaf(d, d, sap);
                    d = avv.z - pv.z + EPS_V; sap = fmaf(d, d, sap);
                    d = avv.w - pv.w + EPS_V; sap = fmaf(d, d, sap);
                    d = avv.x - nv.x + EPS_V; san = fmaf(d, d, san);
                    d = avv.y - nv.y + EPS_V; san = fmaf(d, d, san);
                    d = avv.z - nv.z + EPS_V; san = fmaf(d, d, san);
                    d = avv.w - nv.w + EPS_V; san = fmaf(d, d, san);
                }
            }
            #pragma unroll
            for (int o = 16; o > 0; o >>= 1) {
                sap += __shfl_xor_sync(0xffffffffu, sap, o);
                san += __shfl_xor_sync(0xffffffffu, san, o);
            }
            per = fmaxf(sqrtf(sap) - sqrtf(san) + MARGIN, 0.0f);
            vld = 1u;
        }
    }

    // ---- deterministic fused reduction tail (integer fixed-point, 2^32) ----
    __shared__ unsigned long long s_q[8];
    __shared__ unsigned int s_c[8];
    __shared__ bool s_last;
    if (lane == 0) {
        s_q[warp] = (unsigned long long)((double)per * 4294967296.0);
        s_c[warp] = vld;
    }
    __syncthreads();
    if (threadIdx.x == 0) {
        unsigned long long q = 0ull; unsigned int c = 0u;
        #pragma unroll
        for (int w = 0; w < 8; w++) { q += s_q[w]; c += s_c[w]; }
        // release-scoped reductions (L2 atomics; no L1 flush)
        asm volatile("red.release.gpu.add.u64 [%0], %1;" :: "l"(&g_sum), "l"(q) : "memory");
        asm volatile("red.release.gpu.add.u32 [%0], %1;" :: "l"(&g_cnt), "r"(c) : "memory");
        unsigned int prev;
        asm volatile("atom.acq_rel.gpu.add.u32 %0, [%1], %2;"
                     : "=r"(prev) : "l"(&g_done), "r"(1u) : "memory");
        s_last = (prev == nblocks - 1u);
    }
    __syncthreads();
    if (!s_last) return;

    // last block: finalize + reset all state to zero for the next replay
    if (threadIdx.x == 0) {
        unsigned long long s; unsigned int c;
        asm volatile("atom.acquire.gpu.add.u64 %0, [%1], 0;" : "=l"(s) : "l"(&g_sum) : "memory");
        asm volatile("atom.acquire.gpu.add.u32 %0, [%1], 0;" : "=r"(c) : "l"(&g_cnt) : "memory");
        out[0] = (c > 0u) ? (float)(((double)s / 4294967296.0) / (double)c) : 0.0f;
        g_sum = 0ull; g_cnt = 0u; g_done = 0u; g_mfirst_enc = 0;
    }
    g_first_enc[threadIdx.x] = 0;   // 256 threads reset 256 entries
}

extern "C" void kernel_launch(void* const* d_in, const int* in_sizes, int n_in,
                              void* d_out, int out_size) {
    const int* z_label = (const int*)d_in[0];
    const int* z_idx   = (const int*)d_in[1];
    const float* z     = (const float*)d_in[2];
    float* out = (float*)d_out;

    const int B = in_sizes[0];
    const int C = in_sizes[2] / B;
    int k = (int)((double)B * 0.01);
    if (k < 2) k = 2;

    const int prep_blocks = (B + 255) / 256;
    prep_kernel<<<prep_blocks, 256>>>(z_label, B);

    const unsigned int nblocks = (unsigned int)((B + 7) / 8);
    {
        cudaLaunchConfig_t cfg = {};
        cfg.gridDim = dim3(nblocks);
        cfg.blockDim = dim3(256);
        cfg.dynamicSmemBytes = 0;
        cfg.stream = 0;
        cudaLaunchAttribute at[1];
        at[0].id = cudaLaunchAttributeProgrammaticStreamSerialization;
        at[0].val.programmaticStreamSerializationAllowed = 1;
        cfg.attrs = at;
        cfg.numAttrs = 1;
        cudaLaunchKernelEx(&cfg, triplet_kernel, z, z_label, z_idx, out, B, C, k, nblocks);
    }
}

// round 7
// speedup vs baseline: 1.3239x; 1.0952x over previous
#include <cuda_runtime.h>
#include <math.h>

#define MARGIN 0.2f
#define EPS_V  1e-6f
#define ENC(i) (0x7FFFFFFF - (i))

// All scratch is zero-init at load AND reset to zero by the last triplet block
// each run, so every graph replay sees the same initial state.
__device__ int                g_first_enc[256];  // 0 = label absent; else ENC(first idx)
__device__ int                g_mfirst_enc;      // 0 = all labels identical
__device__ unsigned long long g_sum;             // fixed-point 2^32 sum of per
__device__ unsigned int       g_cnt;             // valid count
__device__ unsigned int       g_done;            // completed-block counter

// ---------------------------------------------------------------------------
// K1: multi-block prep. Global atomics spread across L2 (no single-SM ATOMS
// bottleneck). first-occurrence per raw label + first index whose label != l0.
// ---------------------------------------------------------------------------
__global__ void __launch_bounds__(256) prep_kernel(const int* __restrict__ label, int B) {
    const int i    = blockIdx.x * 256 + threadIdx.x;
    const int lane = threadIdx.x & 31;
    const int l0   = __ldg(&label[0]);

    const int lab = (i < B) ? __ldg(&label[i]) : l0;
    if (i < B)
        atomicMax(&g_first_enc[lab & 255], ENC(i));

    unsigned m = __ballot_sync(0xffffffffu, (i < B) && (lab != l0));
    if (lane == 0 && m) {
        int j = (i - lane) + __ffs(m) - 1;
        atomicMax(&g_mfirst_enc, ENC(j));
    }
}

// ---------------------------------------------------------------------------
// K2: one warp per row + FENCE-FREE deterministic fused reduction tail.
// Integer fixed-point sums via relaxed atomics with return; completion of each
// block's sum-adds is ordered before its done++ via a data-dependent predicate
// (no gpu-scope release -> no CCTL.IVALL -> L1 stays warm for pos/neg rows).
// ---------------------------------------------------------------------------
__global__ void __launch_bounds__(256) triplet_kernel(const float* __restrict__ z,
                                                      const int* __restrict__ label,
                                                      const int* __restrict__ zidx,
                                                      float* __restrict__ out,
                                                      int B, int C, int k,
                                                      unsigned int nblocks) {
    const int warp = threadIdx.x >> 5;
    const int lane = threadIdx.x & 31;
    const int i = blockIdx.x * 8 + warp;

    // ---- independent of prep: prefetch a-row + scalars (overlaps prep) ----
    float4 av[8];
    const bool fast = (C == 1024) && (i < B);
    const float4* a = (const float4*)(z + (size_t)((i < B) ? i : 0) * C);
    if (fast) {
        #pragma unroll
        for (int u = 0; u < 8; u++)
            av[u] = a[lane + (u << 5)];
    }
    const int lab_i = (i < B) ? __ldg(&label[i]) : 0;
    const int l0    = __ldg(&label[0]);
    const int idx_i = (i < B) ? __ldg(&zidx[i]) : 0;

    // ---- wait for prep ----
    cudaGridDependencySynchronize();

    float per = 0.0f;
    unsigned int vld = 0u;

    if (i < B) {
        const bool allsame = (g_mfirst_enc == 0);
        int pos = -1, neg = -1;

        if (!allsame) {
            const int f = 0x7FFFFFFF - g_first_enc[lab_i & 255];
            if (f != i) {
                pos = f;
                if (__ldg(&zidx[f]) == idx_i) pos = -1;   // degenerate
            }
            if (pos < 0) {
                // i is the first occurrence: scan forward for the 2nd (rare)
                for (int base = i + 1; base < B; base += 32) {
                    int j = base + lane;
                    bool ok = false;
                    if (j < B)
                        ok = (__ldg(&label[j]) == lab_i) && (__ldg(&zidx[j]) != idx_i);
                    unsigned m = __ballot_sync(0xffffffffu, ok);
                    if (m) { pos = base + __ffs(m) - 1; break; }
                }
            }
            neg = (lab_i != l0) ? 0 : (0x7FFFFFFF - g_mfirst_enc);
        } else {
            // all labels equal: effective labels are -1 for j<k, l0 otherwise
            if (i < k) { pos = (i == 0) ? 1 : 0;       neg = k; }
            else       { pos = (i == k) ? (k + 1) : k; neg = 0; }
            if (pos >= B || neg >= B || k < 2) { pos = -1; }
        }

        if (pos >= 0 && pos < B && neg >= 0 && neg < B) {
            const float4* p = (const float4*)(z + (size_t)pos * C);
            const float4* n = (const float4*)(z + (size_t)neg * C);
            float sap = 0.0f, san = 0.0f;
            if (fast) {
                #pragma unroll
                for (int u = 0; u < 8; u++) {
                    const int v = lane + (u << 5);
                    float4 pv = __ldg(&p[v]);
                    float4 nv = __ldg(&n[v]);
                    float d;
                    d = av[u].x - pv.x + EPS_V; sap = fmaf(d, d, sap);
                    d = av[u].y - pv.y + EPS_V; sap = fmaf(d, d, sap);
                    d = av[u].z - pv.z + EPS_V; sap = fmaf(d, d, sap);
                    d = av[u].w - pv.w + EPS_V; sap = fmaf(d, d, sap);
                    d = av[u].x - nv.x + EPS_V; san = fmaf(d, d, san);
                    d = av[u].y - nv.y + EPS_V; san = fmaf(d, d, san);
                    d = av[u].z - nv.z + EPS_V; san = fmaf(d, d, san);
                    d = av[u].w - nv.w + EPS_V; san = fmaf(d, d, san);
                }
            } else {
                const int nvec = C >> 2;
                for (int v = lane; v < nvec; v += 32) {
                    float4 avv = a[v];
                    float4 pv = __ldg(&p[v]);
                    float4 nv = __ldg(&n[v]);
                    float d;
                    d = avv.x - pv.x + EPS_V; sap = fmaf(d, d, sap);
                    d = avv.y - pv.y + EPS_V; sap = fmaf(d, d, sap);
                    d = avv.z - pv.z + EPS_V; sap = fmaf(d, d, sap);
                    d = avv.w - pv.w + EPS_V; sap = fmaf(d, d, sap);
                    d = avv.x - nv.x + EPS_V; san = fmaf(d, d, san);
                    d = avv.y - nv.y + EPS_V; san = fmaf(d, d, san);
                    d = avv.z - nv.z + EPS_V; san = fmaf(d, d, san);
                    d = avv.w - nv.w + EPS_V; san = fmaf(d, d, san);
                }
            }
            #pragma unroll
            for (int o = 16; o > 0; o >>= 1) {
                sap += __shfl_xor_sync(0xffffffffu, sap, o);
                san += __shfl_xor_sync(0xffffffffu, san, o);
            }
            per = fmaxf(sqrtf(sap) - sqrtf(san) + MARGIN, 0.0f);
            vld = 1u;
        }
    }

    // ---- fence-free deterministic reduction tail ----
    __shared__ unsigned long long s_q[8];
    __shared__ unsigned int s_c[8];
    __shared__ bool s_last;
    if (lane == 0) {
        s_q[warp] = (unsigned long long)((double)per * 4294967296.0);
        s_c[warp] = vld;
    }
    __syncthreads();
    if (threadIdx.x == 0) {
        unsigned long long q = 0ull; unsigned int c = 0u;
        #pragma unroll
        for (int w = 0; w < 8; w++) { q += s_q[w]; c += s_c[w]; }

        unsigned int prev;
        // Relaxed atomics WITH return; the done++ is predicated on values
        // derived from the returned old sums (predicates are always-true at
        // runtime but not compile-time foldable), so each block's sum commits
        // at L2 before its done++ becomes visible. No fences, no L1 flush.
        asm volatile(
            "{\n\t"
            ".reg .pred p;\n\t"
            ".reg .u64 oq;\n\t"
            ".reg .u32 oc, od;\n\t"
            "atom.relaxed.gpu.global.add.u64 oq, [%1], %3;\n\t"
            "atom.relaxed.gpu.global.add.u32 oc, [%2], %4;\n\t"
            "setp.ne.u64 p, oq, 0xffffffffffffffff;\n\t"
            "setp.ne.and.u32 p, oc, 0xffffffff, p;\n\t"
            "@p  atom.relaxed.gpu.global.add.u32 od, [%5], 1;\n\t"
            "@!p atom.relaxed.gpu.global.add.u32 od, [%5], 1;\n\t"
            "mov.u32 %0, od;\n\t"
            "}"
            : "=r"(prev)
            : "l"(&g_sum), "l"(&g_cnt), "l"(q), "r"(c), "l"(&g_done)
            : "memory");
        s_last = (prev == nblocks - 1u);
    }
    __syncthreads();
    if (!s_last) return;

    // last block: all other blocks' sums are committed at L2 (their done++
    // happened after their sum-adds completed). Read via relaxed atomics
    // (bypass L1), finalize, and reset all state for the next graph replay.
    if (threadIdx.x == 0) {
        unsigned long long s; unsigned int c;
        asm volatile("atom.relaxed.gpu.global.add.u64 %0, [%1], 0;"
                     : "=l"(s) : "l"(&g_sum) : "memory");
        asm volatile("atom.relaxed.gpu.global.add.u32 %0, [%1], 0;"
                     : "=r"(c) : "l"(&g_cnt) : "memory");
        out[0] = (c > 0u) ? (float)(((double)s / 4294967296.0) / (double)c) : 0.0f;
        g_sum = 0ull; g_cnt = 0u; g_done = 0u; g_mfirst_enc = 0;
    }
    g_first_enc[threadIdx.x] = 0;   // 256 threads reset 256 entries
}

extern "C" void kernel_launch(void* const* d_in, const int* in_sizes, int n_in,
                              void* d_out, int out_size) {
    const int* z_label = (const int*)d_in[0];
    const int* z_idx   = (const int*)d_in[1];
    const float* z     = (const float*)d_in[2];
    float* out = (float*)d_out;

    const int B = in_sizes[0];
    const int C = in_sizes[2] / B;
    int k = (int)((double)B * 0.01);
    if (k < 2) k = 2;

    const int prep_blocks = (B + 255) / 256;
    prep_kernel<<<prep_blocks, 256>>>(z_label, B);

    const unsigned int nblocks = (unsigned int)((B + 7) / 8);
    {
        cudaLaunchConfig_t cfg = {};
        cfg.gridDim = dim3(nblocks);
        cfg.blockDim = dim3(256);
        cfg.dynamicSmemBytes = 0;
        cfg.stream = 0;
        cudaLaunchAttribute at[1];
        at[0].id = cudaLaunchAttributeProgrammaticStreamSerialization;
        at[0].val.programmaticStreamSerializationAllowed = 1;
        cfg.attrs = at;
        cfg.numAttrs = 1;
        cudaLaunchKernelEx(&cfg, triplet_kernel, z, z_label, z_idx, out, B, C, k, nblocks);
    }
}

// round 8
// speedup vs baseline: 1.3395x; 1.0118x over previous
#include <cuda_runtime.h>
#include <math.h>

#define MARGIN 0.2f
#define EPS_V  1e-6f
#define ENC(i) (0x7FFFFFFF - (i))

// Packed accumulator: bits[0:38) sum_q (fixed-point 2^16),
//                     bits[38:52) valid count, bits[52:63) done-block count.
#define SUM_BITS   38
#define CNT_SHIFT  38
#define DONE_SHIFT 52
#define SUM_MASK   ((1ull << SUM_BITS) - 1ull)
#define CNT_MASK   ((1ull << (DONE_SHIFT - CNT_SHIFT)) - 1ull)
#define FIXP       65536.0

// Zero-init at load; last triplet block resets everything each run so every
// graph replay sees identical initial state.
__device__ int                g_first_enc[256];  // 0 = absent; else ENC(first idx)
__device__ int                g_mfirst_enc;      // 0 = all labels identical
__device__ unsigned long long g_acc;             // packed sum|cnt|done

// ---------------------------------------------------------------------------
// K1: multi-block prep. Global atomics spread across L2.
// ---------------------------------------------------------------------------
__global__ void __launch_bounds__(256) prep_kernel(const int* __restrict__ label, int B) {
    const int i    = blockIdx.x * 256 + threadIdx.x;
    const int lane = threadIdx.x & 31;
    const int l0   = __ldg(&label[0]);

    const int lab = (i < B) ? __ldg(&label[i]) : l0;
    if (i < B)
        atomicMax(&g_first_enc[lab & 255], ENC(i));

    unsigned m = __ballot_sync(0xffffffffu, (i < B) && (lab != l0));
    if (lane == 0 && m) {
        int j = (i - lane) + __ffs(m) - 1;
        atomicMax(&g_mfirst_enc, ENC(j));
    }
}

// ---------------------------------------------------------------------------
// K2: one warp per row + single-atomic deterministic fused reduction tail.
// ---------------------------------------------------------------------------
__global__ void __launch_bounds__(256) triplet_kernel(const float* __restrict__ z,
                                                      const int* __restrict__ label,
                                                      const int* __restrict__ zidx,
                                                      float* __restrict__ out,
                                                      int B, int C, int k,
                                                      unsigned int nblocks) {
    const int warp = threadIdx.x >> 5;
    const int lane = threadIdx.x & 31;
    const int i = blockIdx.x * 8 + warp;

    // ---- independent of prep: prefetch a-row + scalars (overlaps prep) ----
    float4 av[8];
    const bool fast = (C == 1024) && (i < B);
    const float4* a = (const float4*)(z + (size_t)((i < B) ? i : 0) * C);
    if (fast) {
        #pragma unroll
        for (int u = 0; u < 8; u++)
            av[u] = a[lane + (u << 5)];
    }
    const int lab_i = (i < B) ? __ldg(&label[i]) : 0;
    const int l0    = __ldg(&label[0]);
    const int idx_i = (i < B) ? __ldg(&zidx[i]) : 0;

    // fold EPS into the a-row once (shorter FMA dep chains)
    if (fast) {
        #pragma unroll
        for (int u = 0; u < 8; u++) {
            av[u].x += EPS_V; av[u].y += EPS_V; av[u].z += EPS_V; av[u].w += EPS_V;
        }
    }

    // ---- wait for prep ----
    cudaGridDependencySynchronize();

    float per = 0.0f;
    unsigned int vld = 0u;

    if (i < B) {
        const bool allsame = (g_mfirst_enc == 0);
        int pos = -1, neg = -1;

        if (!allsame) {
            const int f = 0x7FFFFFFF - g_first_enc[lab_i & 255];
            if (f != i) {
                pos = f;
                if (__ldg(&zidx[f]) == idx_i) pos = -1;   // degenerate zidx dup
            }
            if (pos < 0) {
                // i is the first occurrence: scan forward for the 2nd (rare)
                for (int base = i + 1; base < B; base += 32) {
                    int j = base + lane;
                    bool ok = false;
                    if (j < B)
                        ok = (__ldg(&label[j]) == lab_i) && (__ldg(&zidx[j]) != idx_i);
                    unsigned m = __ballot_sync(0xffffffffu, ok);
                    if (m) { pos = base + __ffs(m) - 1; break; }
                }
            }
            neg = (lab_i != l0) ? 0 : (0x7FFFFFFF - g_mfirst_enc);
        } else {
            // all labels equal: effective labels are -1 for j<k, l0 otherwise
            if (i < k) { pos = (i == 0) ? 1 : 0;       neg = k; }
            else       { pos = (i == k) ? (k + 1) : k; neg = 0; }
            if (pos >= B || neg >= B || k < 2) { pos = -1; }
        }

        if (pos >= 0 && pos < B && neg >= 0 && neg < B) {
            const float4* p = (const float4*)(z + (size_t)pos * C);
            const float4* n = (const float4*)(z + (size_t)neg * C);
            float sap = 0.0f, san = 0.0f;
            if (fast) {
                #pragma unroll
                for (int u = 0; u < 8; u++) {
                    const int v = lane + (u << 5);
                    float4 pv = __ldg(&p[v]);
                    float4 nv = __ldg(&n[v]);
                    float d;
                    d = av[u].x - pv.x; sap = fmaf(d, d, sap);
                    d = av[u].y - pv.y; sap = fmaf(d, d, sap);
                    d = av[u].z - pv.z; sap = fmaf(d, d, sap);
                    d = av[u].w - pv.w; sap = fmaf(d, d, sap);
                    d = av[u].x - nv.x; san = fmaf(d, d, san);
                    d = av[u].y - nv.y; san = fmaf(d, d, san);
                    d = av[u].z - nv.z; san = fmaf(d, d, san);
                    d = av[u].w - nv.w; san = fmaf(d, d, san);
                }
            } else {
                const int nvec = C >> 2;
                for (int v = lane; v < nvec; v += 32) {
                    float4 avv = a[v];
                    float4 pv = __ldg(&p[v]);
                    float4 nv = __ldg(&n[v]);
                    float d;
                    d = avv.x - pv.x + EPS_V; sap = fmaf(d, d, sap);
                    d = avv.y - pv.y + EPS_V; sap = fmaf(d, d, sap);
                    d = avv.z - pv.z + EPS_V; sap = fmaf(d, d, sap);
                    d = avv.w - pv.w + EPS_V; sap = fmaf(d, d, sap);
                    d = avv.x - nv.x + EPS_V; san = fmaf(d, d, san);
                    d = avv.y - nv.y + EPS_V; san = fmaf(d, d, san);
                    d = avv.z - nv.z + EPS_V; san = fmaf(d, d, san);
                    d = avv.w - nv.w + EPS_V; san = fmaf(d, d, san);
                }
            }
            #pragma unroll
            for (int o = 16; o > 0; o >>= 1) {
                sap += __shfl_xor_sync(0xffffffffu, sap, o);
                san += __shfl_xor_sync(0xffffffffu, san, o);
            }
            per = fmaxf(sqrtf(sap) - sqrtf(san) + MARGIN, 0.0f);
            vld = 1u;
        }
    }

    // ---- single-atomic deterministic tail ----
    __shared__ float s_s[8];
    __shared__ unsigned int s_c[8];
    __shared__ bool s_last;
    __shared__ unsigned long long s_total;
    if (lane == 0) { s_s[warp] = per; s_c[warp] = vld; }
    __syncthreads();
    if (threadIdx.x == 0) {
        double bsum = 0.0; unsigned int c = 0u;
        #pragma unroll
        for (int w = 0; w < 8; w++) { bsum += (double)s_s[w]; c += s_c[w]; }
        unsigned long long q = (unsigned long long)(bsum * FIXP + 0.5);
        unsigned long long val = q
                               | ((unsigned long long)c << CNT_SHIFT)
                               | (1ull << DONE_SHIFT);
        unsigned long long old = atomicAdd(&g_acc, val);   // relaxed, no fence
        s_last  = ((old >> DONE_SHIFT) == (unsigned long long)(nblocks - 1u));
        s_total = old + val;
    }
    __syncthreads();
    if (!s_last) return;

    // last block: the packed word already holds the final sums
    if (threadIdx.x == 0) {
        unsigned long long t = s_total;
        unsigned long long sq = t & SUM_MASK;
        unsigned int c = (unsigned int)((t >> CNT_SHIFT) & CNT_MASK);
        out[0] = (c > 0u) ? (float)(((double)sq / FIXP) / (double)c) : 0.0f;
        g_acc = 0ull;
        g_mfirst_enc = 0;
    }
    g_first_enc[threadIdx.x] = 0;   // 256 threads reset the table
}

extern "C" void kernel_launch(void* const* d_in, const int* in_sizes, int n_in,
                              void* d_out, int out_size) {
    const int* z_label = (const int*)d_in[0];
    const int* z_idx   = (const int*)d_in[1];
    const float* z     = (const float*)d_in[2];
    float* out = (float*)d_out;

    const int B = in_sizes[0];
    const int C = in_sizes[2] / B;
    int k = (int)((double)B * 0.01);
    if (k < 2) k = 2;

    const int prep_blocks = (B + 255) / 256;
    prep_kernel<<<prep_blocks, 256>>>(z_label, B);

    const unsigned int nblocks = (unsigned int)((B + 7) / 8);
    {
        cudaLaunchConfig_t cfg = {};
        cfg.gridDim = dim3(nblocks);
        cfg.blockDim = dim3(256);
        cfg.dynamicSmemBytes = 0;
        cfg.stream = 0;
        cudaLaunchAttribute at[1];
        at[0].id = cudaLaunchAttributeProgrammaticStreamSerialization;
        at[0].val.programmaticStreamSerializationAllowed = 1;
        cfg.attrs = at;
        cfg.numAttrs = 1;
        cudaLaunchKernelEx(&cfg, triplet_kernel, z, z_label, z_idx, out, B, C, k, nblocks);
    }
}